// round 14
// baseline (speedup 1.0000x reference)
#include <cuda_runtime.h>
#include <cuda_bf16.h>
#include <cstdint>

#define NN 100000
#define NE 1600000
#define DD 128
#define NG 64
#define SCAN_B 1024
#define NSCAN ((NN + SCAN_B - 1) / SCAN_B)   // 98

// ---------------- device scratch ----------------
// g_cnt invariant: zero at entry of every kernel_launch invocation
// (zero-initialized at load; k_scatter decrements it back to zero).
__device__ int      g_cnt[NN];
__device__ int      g_off[NN + 1];
__device__ int      g_bsum[NSCAN];
__device__ int      g_src[NE];
__device__ float    g_a[NN * DD];         // m = h + agg (fp32)
__device__ float    g_h[NN * DD];         // layer output (fp32)
__device__ uint32_t g_wth[6 * 128 * 64];  // W^T split hi: [mat][n][k-pairs]
__device__ uint32_t g_wtl[6 * 128 * 64];  // W^T split lo

// ---------------- helpers ----------------
__device__ __forceinline__ void atomicMaxF(float* a, float v) {
    if (v >= 0.0f) atomicMax((int*)a, __float_as_int(v));
    else           atomicMin((unsigned int*)a, __float_as_uint(v));
}

// split fp32 -> bf16 hi + bf16 lo (residual), packed as bf16x2 pairs
__device__ __forceinline__ void split2(float x, float y, uint32_t& hi, uint32_t& lo) {
    __nv_bfloat16 hx = __float2bfloat16_rn(x);
    __nv_bfloat16 hy = __float2bfloat16_rn(y);
    __nv_bfloat16 lx = __float2bfloat16_rn(x - __bfloat162float(hx));
    __nv_bfloat16 ly = __float2bfloat16_rn(y - __bfloat162float(hy));
    __nv_bfloat162 h(hx, hy), l(lx, ly);
    hi = *reinterpret_cast<uint32_t*>(&h);
    lo = *reinterpret_cast<uint32_t*>(&l);
}

__device__ __forceinline__ void mma_bf16(float* c, const uint32_t* a, const uint32_t* b) {
    asm volatile(
        "mma.sync.aligned.m16n8k16.row.col.f32.bf16.bf16.f32 "
        "{%0,%1,%2,%3}, {%4,%5,%6,%7}, {%8,%9}, {%0,%1,%2,%3};"
        : "+f"(c[0]), "+f"(c[1]), "+f"(c[2]), "+f"(c[3])
        : "r"(a[0]), "r"(a[1]), "r"(a[2]), "r"(a[3]), "r"(b[0]), "r"(b[1]));
}

__device__ __forceinline__ void ldsm_x4(uint32_t r[4], const char* p) {
    uint32_t a = (uint32_t)__cvta_generic_to_shared(p);
    asm volatile("ldmatrix.sync.aligned.m8n8.x4.shared.b16 {%0,%1,%2,%3}, [%4];"
        : "=r"(r[0]), "=r"(r[1]), "=r"(r[2]), "=r"(r[3]) : "r"(a));
}

// ---------------- weight pre-split: W[k][n] -> Wt[n][k] bf16 hi/lo ----------------
__global__ void k_splitW(const float* __restrict__ W1, const float* __restrict__ W2) {
    int m = blockIdx.x;   // 0..5: 0-2 = W1[l], 3-5 = W2[l-3]
    const float* __restrict__ W = (m < 3) ? (W1 + m * 16384) : (W2 + (m - 3) * 16384);
    uint32_t* th = g_wth + m * 8192;
    uint32_t* tl = g_wtl + m * 8192;
    for (int idx = threadIdx.x; idx < 8192; idx += blockDim.x) {
        int n = idx >> 6;       // 0..127
        int p = idx & 63;       // u32 pair -> k = 2p, 2p+1
        float w0 = __ldg(&W[(2 * p) * DD + n]);
        float w1 = __ldg(&W[(2 * p + 1) * DD + n]);
        uint32_t hi, lo;
        split2(w0, w1, hi, lo);
        th[n * 64 + p] = hi;
        tl[n * 64 + p] = lo;
    }
}

// ---------------- CSR build ----------------
__global__ void k_hist(const int* __restrict__ dst) {
    int e = blockIdx.x * blockDim.x + threadIdx.x;
    if (e < NE) atomicAdd(&g_cnt[dst[e]], 1);
}
__global__ void k_scan1() {
    __shared__ int sh[SCAN_B];
    int tid = threadIdx.x;
    int i = blockIdx.x * SCAN_B + tid;
    int v = (i < NN) ? g_cnt[i] : 0;
    sh[tid] = v;
    __syncthreads();
    for (int off = 1; off < SCAN_B; off <<= 1) {
        int tmp = 0;
        if (tid >= off) tmp = sh[tid - off];
        __syncthreads();
        if (tid >= off) sh[tid] += tmp;
        __syncthreads();
    }
    if (i < NN) g_off[i] = sh[tid] - v;
    if (tid == SCAN_B - 1) g_bsum[blockIdx.x] = sh[tid];
}
// merged scan2+scan3: every block redundantly scans the 98 block sums
__global__ void k_scan23() {
    __shared__ int s2[128];
    int tid = threadIdx.x;
    if (tid < 128) s2[tid] = (tid < NSCAN) ? g_bsum[tid] : 0;
    __syncthreads();
    for (int off = 1; off < 128; off <<= 1) {
        int tmp = 0;
        if (tid < 128 && tid >= off) tmp = s2[tid - off];
        __syncthreads();
        if (tid < 128 && tid >= off) s2[tid] += tmp;
        __syncthreads();
    }
    int i = blockIdx.x * blockDim.x + tid;
    if (i < NN) {
        int blk = i / SCAN_B;
        g_off[i] += (blk > 0) ? s2[blk - 1] : 0;
    } else if (i == NN) {
        g_off[NN] = NE;
    }
}
// decrement-scatter: leaves g_cnt back at 0 for the next invocation
__global__ void k_scatter(const int* __restrict__ src, const int* __restrict__ dst) {
    int e = blockIdx.x * blockDim.x + threadIdx.x;
    if (e < NE) {
        int d = dst[e];
        int p = g_off[d] + atomicSub(&g_cnt[d], 1) - 1;
        g_src[p] = src[e];
    }
}

// ---------------- aggregation: warp per node, float4, 2x unrolled ----------------
__global__ void k_agg(const float* __restrict__ x, int use_x) {
    const float4* __restrict__ hin = (const float4*)(use_x ? x : (const float*)g_h);
    int node = blockIdx.x * 4 + (threadIdx.x >> 5);
    if (node >= NN) return;
    int lane = threadIdx.x & 31;
    float4 a0 = __ldg(&hin[node * 32 + lane]);
    float4 a1 = make_float4(0.f, 0.f, 0.f, 0.f);
    int e   = g_off[node];
    int end = g_off[node + 1];
    for (; e + 2 <= end; e += 2) {
        int s0 = __ldg(&g_src[e]);
        int s1 = __ldg(&g_src[e + 1]);
        float4 v0 = __ldg(&hin[s0 * 32 + lane]);
        float4 v1 = __ldg(&hin[s1 * 32 + lane]);
        a0.x += v0.x; a0.y += v0.y; a0.z += v0.z; a0.w += v0.w;
        a1.x += v1.x; a1.y += v1.y; a1.z += v1.z; a1.w += v1.w;
    }
    if (e < end) {
        int s = __ldg(&g_src[e]);
        float4 v = __ldg(&hin[s * 32 + lane]);
        a0.x += v.x; a0.y += v.y; a0.z += v.z; a0.w += v.w;
    }
    a0.x += a1.x; a0.y += a1.y; a0.z += a1.z; a0.w += a1.w;
    ((float4*)g_a)[node * 32 + lane] = a0;
}

// ---------------- fused MLP layer: g_h = act2(relu(g_a@W1+b1)@W2 + b2) ----------------
#define AP1 72                       // chunk row pad (bf16 elems), 144B rows
#define TILE1 (128 * AP1 * 2)        // 18432 B
#define AP2 136                      // T row pad, 272B rows
#define TILET (128 * AP2 * 2)        // 34816 B
#define O_A1H 0
#define O_A1L TILE1
#define O_B1H (2 * TILE1)
#define O_B1L (3 * TILE1)
#define O_TH  0
#define O_TL  TILET
#define O_B2H (2 * TILET)            // 69632
#define O_B2L (2 * TILET + TILE1)    // 88064
#define SM_LAYER (2 * TILET + 2 * TILE1)   // 106496

// one k16 MMA step (3-term split)
__device__ __forceinline__ void mma_step(
    float acc[4][4][4], const char* sm_, int oAh, int oAl, int APa, int acol,
    int oBh, int oBl, int kk, int wm, int wn, int lane)
{
    uint32_t bh[4][2], bl[4][2], t[4];
    int brow = wn * 32 + ((lane >> 4) << 3) + (lane & 7);
    int bcol = kk + (((lane >> 3) & 1) << 3);
    #pragma unroll
    for (int np = 0; np < 2; np++) {
        const char* ph = sm_ + oBh + ((brow + np * 16) * AP1 + bcol) * 2;
        const char* pl = sm_ + oBl + ((brow + np * 16) * AP1 + bcol) * 2;
        ldsm_x4(t, ph);
        bh[np * 2][0] = t[0]; bh[np * 2][1] = t[1];
        bh[np * 2 + 1][0] = t[2]; bh[np * 2 + 1][1] = t[3];
        ldsm_x4(t, pl);
        bl[np * 2][0] = t[0]; bl[np * 2][1] = t[1];
        bl[np * 2 + 1][0] = t[2]; bl[np * 2 + 1][1] = t[3];
    }
    int arow = wm * 64 + (lane & 15);
    int acl  = acol + kk + ((lane >> 4) << 3);
    #pragma unroll
    for (int mt = 0; mt < 4; mt++) {
        uint32_t ah[4], al[4];
        ldsm_x4(ah, sm_ + oAh + ((arow + mt * 16) * APa + acl) * 2);
        ldsm_x4(al, sm_ + oAl + ((arow + mt * 16) * APa + acl) * 2);
        #pragma unroll
        for (int nt = 0; nt < 4; nt++) {
            mma_bf16(acc[mt][nt], ah, bh[nt]);   // hi*hi
            mma_bf16(acc[mt][nt], ah, bl[nt]);   // hi*lo
            mma_bf16(acc[mt][nt], al, bh[nt]);   // lo*hi
        }
    }
}

// copy one 64-k chunk of pre-split W^T into SMEM B tile (same addressing as R4 loads)
__device__ __forceinline__ void load_B_chunk(char* sm_, int oBh, int oBl,
                                             int mat, int h, int tid) {
    const uint32_t* __restrict__ th = g_wth + mat * 8192 + h * 32;
    const uint32_t* __restrict__ tl = g_wtl + mat * 8192 + h * 32;
    #pragma unroll
    for (int i = 0; i < 8; i++) {
        int f  = i * 256 + tid;
        int n  = f & 127;
        int p2 = (f >> 7) << 1;          // u32 pair index (k4/2), 0,2,...,30
        uint2 hh = *(const uint2*)&th[n * 64 + p2];
        uint2 ll = *(const uint2*)&tl[n * 64 + p2];
        int off = (n * AP1 + p2 * 2) * 2;
        *(uint2*)(sm_ + oBh + off) = hh;
        *(uint2*)(sm_ + oBl + off) = ll;
    }
}

__global__ void __launch_bounds__(256, 2)
k_layer(const float* __restrict__ b1, const float* __restrict__ b2,
        int l, int do_relu2) {
    extern __shared__ char sm_[];
    int tid  = threadIdx.x;
    int lane = tid & 31;
    int w    = tid >> 5;
    int wm   = w >> 2;
    int wn   = w & 3;
    int g    = lane >> 2;
    int tig  = lane & 3;
    int row0 = blockIdx.x * 128;

    float acc[4][4][4];
    #pragma unroll
    for (int i = 0; i < 4; i++)
        #pragma unroll
        for (int j = 0; j < 4; j++)
            #pragma unroll
            for (int q = 0; q < 4; q++) acc[i][j][q] = 0.0f;

    // ================= phase 1: acc = g_a @ W1 =================
    for (int h = 0; h < 2; h++) {
        // A chunk: 128 rows x 64 k from g_a (fp32 -> split bf16 hi/lo)
        #pragma unroll
        for (int i = 0; i < 8; i++) {
            int f  = i * 256 + tid;
            int m  = f >> 4;
            int k4 = (f & 15) << 2;
            float4 v = make_float4(0.f, 0.f, 0.f, 0.f);
            int gr = row0 + m;
            if (gr < NN) v = *(const float4*)&g_a[gr * DD + h * 64 + k4];
            uint2 hh, ll;
            split2(v.x, v.y, hh.x, ll.x);
            split2(v.z, v.w, hh.y, ll.y);
            int off = (m * AP1 + k4) * 2;
            *(uint2*)(sm_ + O_A1H + off) = hh;
            *(uint2*)(sm_ + O_A1L + off) = ll;
        }
        load_B_chunk(sm_, O_B1H, O_B1L, l, h, tid);
        __syncthreads();
        #pragma unroll
        for (int ks = 0; ks < 4; ks++)
            mma_step(acc, sm_, O_A1H, O_A1L, AP1, 0, O_B1H, O_B1L, ks * 16, wm, wn, lane);
        __syncthreads();   // before T/next chunk overwrites
    }

    // ================= T = relu(acc + b1) -> split into T region =================
    #pragma unroll
    for (int nt = 0; nt < 4; nt++) {
        int c = wn * 32 + nt * 8 + tig * 2;
        float bb0 = __ldg(&b1[c]);
        float bb1 = __ldg(&b1[c + 1]);
        #pragma unroll
        for (int mt = 0; mt < 4; mt++) {
            float v0 = fmaxf(acc[mt][nt][0] + bb0, 0.f);
            float v1 = fmaxf(acc[mt][nt][1] + bb1, 0.f);
            float v2 = fmaxf(acc[mt][nt][2] + bb0, 0.f);
            float v3 = fmaxf(acc[mt][nt][3] + bb1, 0.f);
            uint32_t h0, l0, h1, l1;
            split2(v0, v1, h0, l0);
            split2(v2, v3, h1, l1);
            int r = wm * 64 + mt * 16 + g;
            *(uint32_t*)(sm_ + O_TH + (r * AP2 + c) * 2) = h0;
            *(uint32_t*)(sm_ + O_TL + (r * AP2 + c) * 2) = l0;
            *(uint32_t*)(sm_ + O_TH + ((r + 8) * AP2 + c) * 2) = h1;
            *(uint32_t*)(sm_ + O_TL + ((r + 8) * AP2 + c) * 2) = l1;
            acc[mt][nt][0] = 0.f; acc[mt][nt][1] = 0.f;
            acc[mt][nt][2] = 0.f; acc[mt][nt][3] = 0.f;
        }
    }

    // ================= phase 2: acc = T @ W2 =================
    for (int h = 0; h < 2; h++) {
        load_B_chunk(sm_, O_B2H, O_B2L, 3 + l, h, tid);
        __syncthreads();   // T stores + B chunk ready
        #pragma unroll
        for (int ks = 0; ks < 4; ks++)
            mma_step(acc, sm_, O_TH, O_TL, AP2, h * 64, O_B2H, O_B2L, ks * 16, wm, wn, lane);
        __syncthreads();
    }

    // ================= epilogue =================
    #pragma unroll
    for (int nt = 0; nt < 4; nt++) {
        int c = wn * 32 + nt * 8 + tig * 2;
        float bb0 = __ldg(&b2[c]);
        float bb1 = __ldg(&b2[c + 1]);
        #pragma unroll
        for (int mt = 0; mt < 4; mt++) {
            int r = row0 + wm * 64 + mt * 16 + g;
            float2 v0 = make_float2(acc[mt][nt][0] + bb0, acc[mt][nt][1] + bb1);
            float2 v1 = make_float2(acc[mt][nt][2] + bb0, acc[mt][nt][3] + bb1);
            if (do_relu2) {
                v0.x = fmaxf(v0.x, 0.f); v0.y = fmaxf(v0.y, 0.f);
                v1.x = fmaxf(v1.x, 0.f); v1.y = fmaxf(v1.y, 0.f);
            }
            if (r < NN)     *(float2*)&g_h[r * DD + c] = v0;
            if (r + 8 < NN) *(float2*)&g_h[(r + 8) * DD + c] = v1;
        }
    }
}

// ---------------- global max pool ----------------
__global__ void k_initout(float* __restrict__ out) {
    int i = blockIdx.x * blockDim.x + threadIdx.x;
    if (i < NG * DD) out[i] = __int_as_float(0xFF800000);
}
__global__ void k_pool(const int* __restrict__ batch, float* __restrict__ out) {
    int t  = threadIdx.x;                 // column 0..127
    int n0 = blockIdx.x * 128;
    int cur = -1;
    float run = __int_as_float(0xFF800000);
    for (int r = 0; r < 128; r++) {
        int i = n0 + r;
        if (i >= NN) break;
        int g = batch[i];
        if (g != cur) {
            if (cur >= 0) atomicMaxF(&out[cur * DD + t], run);
            cur = g;
            run = __int_as_float(0xFF800000);
        }
        run = fmaxf(run, g_h[i * DD + t]);
    }
    if (cur >= 0) atomicMaxF(&out[cur * DD + t], run);
}

// ---------------- launch ----------------
extern "C" void kernel_launch(void* const* d_in, const int* in_sizes, int n_in,
                              void* d_out, int out_size) {
    const float* x     = (const float*)d_in[0];
    const int*   ei    = (const int*)d_in[1];
    const int*   batch = (const int*)d_in[2];
    const float* W1    = (const float*)d_in[3];
    const float* b1    = (const float*)d_in[4];
    const float* W2    = (const float*)d_in[5];
    const float* b2    = (const float*)d_in[6];
    float* out = (float*)d_out;

    const int* src = ei;
    const int* dst = ei + NE;

    cudaFuncSetAttribute(k_layer, cudaFuncAttributeMaxDynamicSharedMemorySize, SM_LAYER);

    // independent prep
    k_initout<<<(NG * DD + 255) / 256, 256>>>(out);
    k_splitW<<<6, 256>>>(W1, W2);

    // CSR build (g_cnt is 0 on entry; scatter restores it to 0)
    k_hist<<<(NE + 255) / 256, 256>>>(dst);
    k_scan1<<<NSCAN, SCAN_B>>>();
    k_scan23<<<(NN + 256) / 256, 256>>>();
    k_scatter<<<(NE + 255) / 256, 256>>>(src, dst);

    // 3 GIN layers: fp32 gather + fused MLP
    int layer_blocks = (NN + 127) / 128;   // 782
    int agg_blocks   = (NN + 3) / 4;
    for (int l = 0; l < 3; l++) {
        k_agg<<<agg_blocks, 128>>>(x, l == 0 ? 1 : 0);
        k_layer<<<layer_blocks, 256, SM_LAYER>>>(b1 + l * DD, b2 + l * DD, l, (l < 2) ? 1 : 0);
    }

    // global max pool
    k_pool<<<(NN + 127) / 128, 128>>>(batch, out);
}

// round 15
// speedup vs baseline: 1.3781x; 1.3781x over previous
#include <cuda_runtime.h>
#include <cuda_bf16.h>
#include <cstdint>

#define NN 100000
#define NE 1600000
#define DD 128
#define NG 64
#define SCAN_B 1024
#define NSCAN ((NN + SCAN_B - 1) / SCAN_B)   // 98

// ---------------- device scratch ----------------
// g_cnt invariant: zero at entry of every kernel_launch invocation
// (zero-initialized at load; k_scatter decrements it back to zero).
__device__ int   g_cnt[NN];
__device__ int   g_off[NN + 1];
__device__ int   g_bsum[NSCAN];
__device__ int   g_src[NE];
__device__ float g_a[NN * DD];   // m = h + agg
__device__ float g_h[NN * DD];   // layer output

// ---------------- helpers ----------------
__device__ __forceinline__ void atomicMaxF(float* a, float v) {
    if (v >= 0.0f) atomicMax((int*)a, __float_as_int(v));
    else           atomicMin((unsigned int*)a, __float_as_uint(v));
}

// split fp32 -> bf16 hi + bf16 lo (residual), packed as bf16x2 pairs
__device__ __forceinline__ void split2(float x, float y, uint32_t& hi, uint32_t& lo) {
    __nv_bfloat16 hx = __float2bfloat16_rn(x);
    __nv_bfloat16 hy = __float2bfloat16_rn(y);
    __nv_bfloat16 lx = __float2bfloat16_rn(x - __bfloat162float(hx));
    __nv_bfloat16 ly = __float2bfloat16_rn(y - __bfloat162float(hy));
    __nv_bfloat162 h(hx, hy), l(lx, ly);
    hi = *reinterpret_cast<uint32_t*>(&h);
    lo = *reinterpret_cast<uint32_t*>(&l);
}

__device__ __forceinline__ void mma_bf16(float* c, const uint32_t* a, const uint32_t* b) {
    asm volatile(
        "mma.sync.aligned.m16n8k16.row.col.f32.bf16.bf16.f32 "
        "{%0,%1,%2,%3}, {%4,%5,%6,%7}, {%8,%9}, {%0,%1,%2,%3};"
        : "+f"(c[0]), "+f"(c[1]), "+f"(c[2]), "+f"(c[3])
        : "r"(a[0]), "r"(a[1]), "r"(a[2]), "r"(a[3]), "r"(b[0]), "r"(b[1]));
}

__device__ __forceinline__ void ldsm_x4(uint32_t r[4], const char* p) {
    uint32_t a = (uint32_t)__cvta_generic_to_shared(p);
    asm volatile("ldmatrix.sync.aligned.m8n8.x4.shared.b16 {%0,%1,%2,%3}, [%4];"
        : "=r"(r[0]), "=r"(r[1]), "=r"(r[2]), "=r"(r[3]) : "r"(a));
}

// ---------------- CSR build ----------------
__global__ void k_hist(const int* __restrict__ dst) {
    int e = blockIdx.x * blockDim.x + threadIdx.x;
    if (e < NE) atomicAdd(&g_cnt[dst[e]], 1);
}
__global__ void k_scan1() {
    __shared__ int sh[SCAN_B];
    int tid = threadIdx.x;
    int i = blockIdx.x * SCAN_B + tid;
    int v = (i < NN) ? g_cnt[i] : 0;
    sh[tid] = v;
    __syncthreads();
    for (int off = 1; off < SCAN_B; off <<= 1) {
        int tmp = 0;
        if (tid >= off) tmp = sh[tid - off];
        __syncthreads();
        if (tid >= off) sh[tid] += tmp;
        __syncthreads();
    }
    if (i < NN) g_off[i] = sh[tid] - v;
    if (tid == SCAN_B - 1) g_bsum[blockIdx.x] = sh[tid];
}
// merged scan2+scan3: every block redundantly scans the 98 block sums
__global__ void k_scan23() {
    __shared__ int s2[128];
    int tid = threadIdx.x;
    if (tid < 128) s2[tid] = (tid < NSCAN) ? g_bsum[tid] : 0;
    __syncthreads();
    for (int off = 1; off < 128; off <<= 1) {
        int tmp = 0;
        if (tid < 128 && tid >= off) tmp = s2[tid - off];
        __syncthreads();
        if (tid < 128 && tid >= off) s2[tid] += tmp;
        __syncthreads();
    }
    int i = blockIdx.x * blockDim.x + tid;
    if (i < NN) {
        int blk = i / SCAN_B;
        g_off[i] += (blk > 0) ? s2[blk - 1] : 0;
    } else if (i == NN) {
        g_off[NN] = NE;
    }
}
// decrement-scatter: leaves g_cnt back at 0 for the next invocation
__global__ void k_scatter(const int* __restrict__ src, const int* __restrict__ dst) {
    int e = blockIdx.x * blockDim.x + threadIdx.x;
    if (e < NE) {
        int d = dst[e];
        int p = g_off[d] + atomicSub(&g_cnt[d], 1) - 1;
        g_src[p] = src[e];
    }
}

// ---------------- aggregation: warp per node, float4, 2x unrolled ----------------
__global__ void k_agg(const float* __restrict__ x, int use_x) {
    const float4* __restrict__ hin = (const float4*)(use_x ? x : (const float*)g_h);
    int node = blockIdx.x * 4 + (threadIdx.x >> 5);
    if (node >= NN) return;
    int lane = threadIdx.x & 31;
    float4 a0 = __ldg(&hin[node * 32 + lane]);
    float4 a1 = make_float4(0.f, 0.f, 0.f, 0.f);
    int beg = g_off[node];
    int end = g_off[node + 1];
    int e = beg;
    for (; e + 2 <= end; e += 2) {
        int s0 = __ldg(&g_src[e]);
        int s1 = __ldg(&g_src[e + 1]);
        float4 v0 = __ldg(&hin[s0 * 32 + lane]);
        float4 v1 = __ldg(&hin[s1 * 32 + lane]);
        a0.x += v0.x; a0.y += v0.y; a0.z += v0.z; a0.w += v0.w;
        a1.x += v1.x; a1.y += v1.y; a1.z += v1.z; a1.w += v1.w;
    }
    if (e < end) {
        int s = __ldg(&g_src[e]);
        float4 v = __ldg(&hin[s * 32 + lane]);
        a0.x += v.x; a0.y += v.y; a0.z += v.z; a0.w += v.w;
    }
    a0.x += a1.x; a0.y += a1.y; a0.z += a1.z; a0.w += a1.w;
    ((float4*)g_a)[node * 32 + lane] = a0;
}

// ---------------- fused GIN layer: g_h = act2((relu(g_a@W1+b1))@W2 + b2) ----------------
#define AP1 72                       // phase-1 row pad (bf16 elems), 144B rows
#define TILE1 (128 * AP1 * 2)        // 18432 B
#define AP2 136                      // T row pad, 272B rows
#define TILET (128 * AP2 * 2)        // 34816 B
#define O_A1H 0
#define O_A1L TILE1
#define O_B1H (2 * TILE1)
#define O_B1L (3 * TILE1)
#define O_TH  0
#define O_TL  TILET
#define O_B2H (2 * TILET)            // 69632
#define O_B2L (2 * TILET + TILE1)    // 88064
#define SM_LAYER (2 * TILET + 2 * TILE1)   // 106496

// one k16 MMA step (3-term split): A from sAh/sAl (row pad APa, col base acol+kk),
// B from sBh/sBl (row pad AP1, col base kk)
__device__ __forceinline__ void mma_step(
    float acc[4][4][4], const char* sm_, int oAh, int oAl, int APa, int acol,
    int oBh, int oBl, int kk, int wm, int wn, int lane)
{
    uint32_t bh[4][2], bl[4][2], t[4];
    int brow = wn * 32 + ((lane >> 4) << 3) + (lane & 7);
    int bcol = kk + (((lane >> 3) & 1) << 3);
    #pragma unroll
    for (int np = 0; np < 2; np++) {
        const char* ph = sm_ + oBh + ((brow + np * 16) * AP1 + bcol) * 2;
        const char* pl = sm_ + oBl + ((brow + np * 16) * AP1 + bcol) * 2;
        ldsm_x4(t, ph);
        bh[np * 2][0] = t[0]; bh[np * 2][1] = t[1];
        bh[np * 2 + 1][0] = t[2]; bh[np * 2 + 1][1] = t[3];
        ldsm_x4(t, pl);
        bl[np * 2][0] = t[0]; bl[np * 2][1] = t[1];
        bl[np * 2 + 1][0] = t[2]; bl[np * 2 + 1][1] = t[3];
    }
    int arow = wm * 64 + (lane & 15);
    int acl  = acol + kk + ((lane >> 4) << 3);
    #pragma unroll
    for (int mt = 0; mt < 4; mt++) {
        uint32_t ah[4], al[4];
        ldsm_x4(ah, sm_ + oAh + ((arow + mt * 16) * APa + acl) * 2);
        ldsm_x4(al, sm_ + oAl + ((arow + mt * 16) * APa + acl) * 2);
        #pragma unroll
        for (int nt = 0; nt < 4; nt++) {
            mma_bf16(acc[mt][nt], ah, bh[nt]);   // hi*hi
            mma_bf16(acc[mt][nt], ah, bl[nt]);   // hi*lo
            mma_bf16(acc[mt][nt], al, bh[nt]);   // lo*hi
        }
    }
}

// load one 64-k chunk of W (as B^T, split hi/lo) into SMEM B tile
__device__ __forceinline__ void load_B_chunk(char* sm_, int oBh, int oBl,
                                             const float* __restrict__ W,
                                             int h, int tid) {
    #pragma unroll
    for (int i = 0; i < 8; i++) {
        int f  = i * 256 + tid;
        int n  = f & 127;
        int k4 = (f >> 7) << 2;
        float w0 = __ldg(&W[(h * 64 + k4 + 0) * DD + n]);
        float w1 = __ldg(&W[(h * 64 + k4 + 1) * DD + n]);
        float w2 = __ldg(&W[(h * 64 + k4 + 2) * DD + n]);
        float w3 = __ldg(&W[(h * 64 + k4 + 3) * DD + n]);
        uint2 hh, ll;
        split2(w0, w1, hh.x, ll.x);
        split2(w2, w3, hh.y, ll.y);
        int off = (n * AP1 + k4) * 2;
        *(uint2*)(sm_ + oBh + off) = hh;
        *(uint2*)(sm_ + oBl + off) = ll;
    }
}

__global__ void __launch_bounds__(256, 2)
k_layer(const float* __restrict__ W1, const float* __restrict__ b1,
        const float* __restrict__ W2, const float* __restrict__ b2,
        int do_relu2) {
    extern __shared__ char sm_[];
    int tid  = threadIdx.x;
    int lane = tid & 31;
    int w    = tid >> 5;
    int wm   = w >> 2;
    int wn   = w & 3;
    int g    = lane >> 2;
    int tig  = lane & 3;
    int row0 = blockIdx.x * 128;

    float acc[4][4][4];
    #pragma unroll
    for (int i = 0; i < 4; i++)
        #pragma unroll
        for (int j = 0; j < 4; j++)
            #pragma unroll
            for (int q = 0; q < 4; q++) acc[i][j][q] = 0.0f;

    // ================= phase 1: acc = g_a @ W1 =================
    for (int h = 0; h < 2; h++) {
        // A chunk: 128 rows x 64 k from g_a
        #pragma unroll
        for (int i = 0; i < 8; i++) {
            int f  = i * 256 + tid;
            int m  = f >> 4;
            int k4 = (f & 15) << 2;
            float4 v = make_float4(0.f, 0.f, 0.f, 0.f);
            int gr = row0 + m;
            if (gr < NN) v = *(const float4*)&g_a[gr * DD + h * 64 + k4];
            uint2 hh, ll;
            split2(v.x, v.y, hh.x, ll.x);
            split2(v.z, v.w, hh.y, ll.y);
            int off = (m * AP1 + k4) * 2;
            *(uint2*)(sm_ + O_A1H + off) = hh;
            *(uint2*)(sm_ + O_A1L + off) = ll;
        }
        load_B_chunk(sm_, O_B1H, O_B1L, W1, h, tid);
        __syncthreads();
        #pragma unroll
        for (int ks = 0; ks < 4; ks++)
            mma_step(acc, sm_, O_A1H, O_A1L, AP1, 0, O_B1H, O_B1L, ks * 16, wm, wn, lane);
        __syncthreads();   // before T overwrites sA/sB regions
    }

    // ================= T = relu(acc + b1)  ->  split into sT =================
    #pragma unroll
    for (int nt = 0; nt < 4; nt++) {
        int c = wn * 32 + nt * 8 + tig * 2;
        float bb0 = __ldg(&b1[c]);
        float bb1 = __ldg(&b1[c + 1]);
        #pragma unroll
        for (int mt = 0; mt < 4; mt++) {
            float v0 = fmaxf(acc[mt][nt][0] + bb0, 0.f);
            float v1 = fmaxf(acc[mt][nt][1] + bb1, 0.f);
            float v2 = fmaxf(acc[mt][nt][2] + bb0, 0.f);
            float v3 = fmaxf(acc[mt][nt][3] + bb1, 0.f);
            uint32_t h0, l0, h1, l1;
            split2(v0, v1, h0, l0);
            split2(v2, v3, h1, l1);
            int r = wm * 64 + mt * 16 + g;
            *(uint32_t*)(sm_ + O_TH + (r * AP2 + c) * 2) = h0;
            *(uint32_t*)(sm_ + O_TL + (r * AP2 + c) * 2) = l0;
            *(uint32_t*)(sm_ + O_TH + ((r + 8) * AP2 + c) * 2) = h1;
            *(uint32_t*)(sm_ + O_TL + ((r + 8) * AP2 + c) * 2) = l1;
            acc[mt][nt][0] = 0.f; acc[mt][nt][1] = 0.f;
            acc[mt][nt][2] = 0.f; acc[mt][nt][3] = 0.f;
        }
    }

    // ================= phase 2: acc = T @ W2 =================
    for (int h = 0; h < 2; h++) {
        load_B_chunk(sm_, O_B2H, O_B2L, W2, h, tid);
        __syncthreads();   // T stores (h=0) / prev-chunk MMA reads (h=1) done
        #pragma unroll
        for (int ks = 0; ks < 4; ks++)
            mma_step(acc, sm_, O_TH, O_TL, AP2, h * 64, O_B2H, O_B2L, ks * 16, wm, wn, lane);
        __syncthreads();
    }

    // ================= epilogue =================
    #pragma unroll
    for (int nt = 0; nt < 4; nt++) {
        int c = wn * 32 + nt * 8 + tig * 2;
        float bb0 = __ldg(&b2[c]);
        float bb1 = __ldg(&b2[c + 1]);
        #pragma unroll
        for (int mt = 0; mt < 4; mt++) {
            int r = row0 + wm * 64 + mt * 16 + g;
            float2 v0 = make_float2(acc[mt][nt][0] + bb0, acc[mt][nt][1] + bb1);
            float2 v1 = make_float2(acc[mt][nt][2] + bb0, acc[mt][nt][3] + bb1);
            if (do_relu2) {
                v0.x = fmaxf(v0.x, 0.f); v0.y = fmaxf(v0.y, 0.f);
                v1.x = fmaxf(v1.x, 0.f); v1.y = fmaxf(v1.y, 0.f);
            }
            if (r < NN)     *(float2*)&g_h[r * DD + c] = v0;
            if (r + 8 < NN) *(float2*)&g_h[(r + 8) * DD + c] = v1;
        }
    }
}

// ---------------- global max pool ----------------
__global__ void k_initout(float* __restrict__ out) {
    int i = blockIdx.x * blockDim.x + threadIdx.x;
    if (i < NG * DD) out[i] = __int_as_float(0xFF800000);
}
__global__ void k_pool(const int* __restrict__ batch, float* __restrict__ out) {
    int t  = threadIdx.x;                 // column 0..127
    int n0 = blockIdx.x * 128;
    int cur = -1;
    float run = __int_as_float(0xFF800000);
    for (int r = 0; r < 128; r++) {
        int i = n0 + r;
        if (i >= NN) break;
        int g = batch[i];
        if (g != cur) {
            if (cur >= 0) atomicMaxF(&out[cur * DD + t], run);
            cur = g;
            run = __int_as_float(0xFF800000);
        }
        run = fmaxf(run, g_h[i * DD + t]);
    }
    if (cur >= 0) atomicMaxF(&out[cur * DD + t], run);
}

// ---------------- launch ----------------
extern "C" void kernel_launch(void* const* d_in, const int* in_sizes, int n_in,
                              void* d_out, int out_size) {
    const float* x     = (const float*)d_in[0];
    const int*   ei    = (const int*)d_in[1];
    const int*   batch = (const int*)d_in[2];
    const float* W1    = (const float*)d_in[3];
    const float* b1    = (const float*)d_in[4];
    const float* W2    = (const float*)d_in[5];
    const float* b2    = (const float*)d_in[6];
    float* out = (float*)d_out;

    const int* src = ei;
    const int* dst = ei + NE;

    cudaFuncSetAttribute(k_layer, cudaFuncAttributeMaxDynamicSharedMemorySize, SM_LAYER);

    // CSR build (g_cnt is 0 on entry; scatter restores it to 0)
    k_hist<<<(NE + 255) / 256, 256>>>(dst);
    k_scan1<<<NSCAN, SCAN_B>>>();
    k_scan23<<<(NN + 256) / 256, 256>>>();
    k_scatter<<<(NE + 255) / 256, 256>>>(src, dst);

    // 3 fused GIN layers
    int layer_blocks = (NN + 127) / 128;   // 782
    int agg_blocks   = (NN + 3) / 4;
    for (int l = 0; l < 3; l++) {
        k_agg<<<agg_blocks, 128>>>(x, l == 0 ? 1 : 0);
        k_layer<<<layer_blocks, 256, SM_LAYER>>>(W1 + l * DD * DD, b1 + l * DD,
                                                 W2 + l * DD * DD, b2 + l * DD,
                                                 (l < 2) ? 1 : 0);
    }

    // global max pool
    k_initout<<<(NG * DD + 255) / 256, 256>>>(out);
    k_pool<<<(NN + 127) / 128, 128>>>(batch, out);
}

// round 17
// speedup vs baseline: 1.5655x; 1.1360x over previous
#include <cuda_runtime.h>
#include <cuda_bf16.h>
#include <cuda_fp16.h>
#include <cstdint>

#define NN 100000
#define NE 1600000
#define DD 128
#define NG 64
#define SCAN_B 1024
#define NSCAN ((NN + SCAN_B - 1) / SCAN_B)   // 98

// ---------------- device scratch ----------------
// g_cnt invariant: zero at entry of every kernel_launch invocation
// (zero-initialized at load; k_scatter decrements it back to zero).
__device__ int    g_cnt[NN];
__device__ int    g_off[NN + 1];
__device__ int    g_bsum[NSCAN];
__device__ int    g_src[NE];
__device__ float  g_a[NN * DD];    // m = h + agg (fp32)
__device__ __half g_hx[NN * DD];   // fp16 copy of input x
__device__ __half g_hh[NN * DD];   // fp16 inter-layer features

// ---------------- helpers ----------------
__device__ __forceinline__ void atomicMaxF(float* a, float v) {
    if (v >= 0.0f) atomicMax((int*)a, __float_as_int(v));
    else           atomicMin((unsigned int*)a, __float_as_uint(v));
}

// split fp32 -> bf16 hi + bf16 lo (residual), packed as bf16x2 pairs
__device__ __forceinline__ void split2(float x, float y, uint32_t& hi, uint32_t& lo) {
    __nv_bfloat16 hx = __float2bfloat16_rn(x);
    __nv_bfloat16 hy = __float2bfloat16_rn(y);
    __nv_bfloat16 lx = __float2bfloat16_rn(x - __bfloat162float(hx));
    __nv_bfloat16 ly = __float2bfloat16_rn(y - __bfloat162float(hy));
    __nv_bfloat162 h(hx, hy), l(lx, ly);
    hi = *reinterpret_cast<uint32_t*>(&h);
    lo = *reinterpret_cast<uint32_t*>(&l);
}

__device__ __forceinline__ void mma_bf16(float* c, const uint32_t* a, const uint32_t* b) {
    asm volatile(
        "mma.sync.aligned.m16n8k16.row.col.f32.bf16.bf16.f32 "
        "{%0,%1,%2,%3}, {%4,%5,%6,%7}, {%8,%9}, {%0,%1,%2,%3};"
        : "+f"(c[0]), "+f"(c[1]), "+f"(c[2]), "+f"(c[3])
        : "r"(a[0]), "r"(a[1]), "r"(a[2]), "r"(a[3]), "r"(b[0]), "r"(b[1]));
}

__device__ __forceinline__ void ldsm_x4(uint32_t r[4], const char* p) {
    uint32_t a = (uint32_t)__cvta_generic_to_shared(p);
    asm volatile("ldmatrix.sync.aligned.m8n8.x4.shared.b16 {%0,%1,%2,%3}, [%4];"
        : "=r"(r[0]), "=r"(r[1]), "=r"(r[2]), "=r"(r[3]) : "r"(a));
}

// unpack 4 fp16 (as uint2) -> float4
__device__ __forceinline__ float4 h2f4(uint2 u) {
    __half2 p0 = *reinterpret_cast<__half2*>(&u.x);
    __half2 p1 = *reinterpret_cast<__half2*>(&u.y);
    float2 f0 = __half22float2(p0);
    float2 f1 = __half22float2(p1);
    return make_float4(f0.x, f0.y, f1.x, f1.y);
}

// ---------------- x -> fp16 convert ----------------
__global__ void k_x2h(const float* __restrict__ x) {
    int i = blockIdx.x * blockDim.x + threadIdx.x;   // float4 groups: NN*32
    if (i < NN * 32) {
        float4 v = __ldg(&((const float4*)x)[i]);
        __half2 h0 = __floats2half2_rn(v.x, v.y);
        __half2 h1 = __floats2half2_rn(v.z, v.w);
        uint2 u;
        u.x = *reinterpret_cast<uint32_t*>(&h0);
        u.y = *reinterpret_cast<uint32_t*>(&h1);
        ((uint2*)g_hx)[i] = u;
    }
}

// ---------------- CSR build ----------------
__global__ void k_hist(const int* __restrict__ dst) {
    int e = blockIdx.x * blockDim.x + threadIdx.x;
    if (e < NE) atomicAdd(&g_cnt[dst[e]], 1);
}
__global__ void k_scan1() {
    __shared__ int sh[SCAN_B];
    int tid = threadIdx.x;
    int i = blockIdx.x * SCAN_B + tid;
    int v = (i < NN) ? g_cnt[i] : 0;
    sh[tid] = v;
    __syncthreads();
    for (int off = 1; off < SCAN_B; off <<= 1) {
        int tmp = 0;
        if (tid >= off) tmp = sh[tid - off];
        __syncthreads();
        if (tid >= off) sh[tid] += tmp;
        __syncthreads();
    }
    if (i < NN) g_off[i] = sh[tid] - v;
    if (tid == SCAN_B - 1) g_bsum[blockIdx.x] = sh[tid];
}
// merged scan2+scan3: every block redundantly scans the 98 block sums
__global__ void k_scan23() {
    __shared__ int s2[128];
    int tid = threadIdx.x;
    if (tid < 128) s2[tid] = (tid < NSCAN) ? g_bsum[tid] : 0;
    __syncthreads();
    for (int off = 1; off < 128; off <<= 1) {
        int tmp = 0;
        if (tid < 128 && tid >= off) tmp = s2[tid - off];
        __syncthreads();
        if (tid < 128 && tid >= off) s2[tid] += tmp;
        __syncthreads();
    }
    int i = blockIdx.x * blockDim.x + tid;
    if (i < NN) {
        int blk = i / SCAN_B;
        g_off[i] += (blk > 0) ? s2[blk - 1] : 0;
    } else if (i == NN) {
        g_off[NN] = NE;
    }
}
// decrement-scatter: leaves g_cnt back at 0 for the next invocation
__global__ void k_scatter(const int* __restrict__ src, const int* __restrict__ dst) {
    int e = blockIdx.x * blockDim.x + threadIdx.x;
    if (e < NE) {
        int d = dst[e];
        int p = g_off[d] + atomicSub(&g_cnt[d], 1) - 1;
        g_src[p] = src[e];
    }
}

// ---------------- aggregation: warp per node, fp16 gather, fp32 accumulate ----------------
// structure identical to R15 (2x unroll, 4 warps/block); only the element type changed
__global__ void k_agg(int use_x) {
    const uint2* __restrict__ hin = use_x ? (const uint2*)g_hx : (const uint2*)g_hh;
    int node = blockIdx.x * 4 + (threadIdx.x >> 5);
    if (node >= NN) return;
    int lane = threadIdx.x & 31;
    float4 a0 = h2f4(__ldg(&hin[node * 32 + lane]));
    float4 a1 = make_float4(0.f, 0.f, 0.f, 0.f);
    int e   = g_off[node];
    int end = g_off[node + 1];
    for (; e + 2 <= end; e += 2) {
        int s0 = __ldg(&g_src[e]);
        int s1 = __ldg(&g_src[e + 1]);
        float4 v0 = h2f4(__ldg(&hin[s0 * 32 + lane]));
        float4 v1 = h2f4(__ldg(&hin[s1 * 32 + lane]));
        a0.x += v0.x; a0.y += v0.y; a0.z += v0.z; a0.w += v0.w;
        a1.x += v1.x; a1.y += v1.y; a1.z += v1.z; a1.w += v1.w;
    }
    if (e < end) {
        int s = __ldg(&g_src[e]);
        float4 v = h2f4(__ldg(&hin[s * 32 + lane]));
        a0.x += v.x; a0.y += v.y; a0.z += v.z; a0.w += v.w;
    }
    a0.x += a1.x; a0.y += a1.y; a0.z += a1.z; a0.w += a1.w;
    ((float4*)g_a)[node * 32 + lane] = a0;
}

// ---------------- fused GIN layer: g_hh = act2((relu(g_a@W1+b1))@W2 + b2) ----------------
#define AP1 72                       // phase-1 row pad (bf16 elems), 144B rows
#define TILE1 (128 * AP1 * 2)        // 18432 B
#define AP2 136                      // T row pad, 272B rows
#define TILET (128 * AP2 * 2)        // 34816 B
#define O_A1H 0
#define O_A1L TILE1
#define O_B1H (2 * TILE1)
#define O_B1L (3 * TILE1)
#define O_TH  0
#define O_TL  TILET
#define O_B2H (2 * TILET)            // 69632
#define O_B2L (2 * TILET + TILE1)    // 88064
#define SM_LAYER (2 * TILET + 2 * TILE1)   // 106496

// one k16 MMA step (3-term split)
__device__ __forceinline__ void mma_step(
    float acc[4][4][4], const char* sm_, int oAh, int oAl, int APa, int acol,
    int oBh, int oBl, int kk, int wm, int wn, int lane)
{
    uint32_t bh[4][2], bl[4][2], t[4];
    int brow = wn * 32 + ((lane >> 4) << 3) + (lane & 7);
    int bcol = kk + (((lane >> 3) & 1) << 3);
    #pragma unroll
    for (int np = 0; np < 2; np++) {
        const char* ph = sm_ + oBh + ((brow + np * 16) * AP1 + bcol) * 2;
        const char* pl = sm_ + oBl + ((brow + np * 16) * AP1 + bcol) * 2;
        ldsm_x4(t, ph);
        bh[np * 2][0] = t[0]; bh[np * 2][1] = t[1];
        bh[np * 2 + 1][0] = t[2]; bh[np * 2 + 1][1] = t[3];
        ldsm_x4(t, pl);
        bl[np * 2][0] = t[0]; bl[np * 2][1] = t[1];
        bl[np * 2 + 1][0] = t[2]; bl[np * 2 + 1][1] = t[3];
    }
    int arow = wm * 64 + (lane & 15);
    int acl  = acol + kk + ((lane >> 4) << 3);
    #pragma unroll
    for (int mt = 0; mt < 4; mt++) {
        uint32_t ah[4], al[4];
        ldsm_x4(ah, sm_ + oAh + ((arow + mt * 16) * APa + acl) * 2);
        ldsm_x4(al, sm_ + oAl + ((arow + mt * 16) * APa + acl) * 2);
        #pragma unroll
        for (int nt = 0; nt < 4; nt++) {
            mma_bf16(acc[mt][nt], ah, bh[nt]);   // hi*hi
            mma_bf16(acc[mt][nt], ah, bl[nt]);   // hi*lo
            mma_bf16(acc[mt][nt], al, bh[nt]);   // lo*hi
        }
    }
}

// load one 64-k chunk of W (as B^T, split hi/lo) into SMEM B tile
__device__ __forceinline__ void load_B_chunk(char* sm_, int oBh, int oBl,
                                             const float* __restrict__ W,
                                             int h, int tid) {
    #pragma unroll
    for (int i = 0; i < 8; i++) {
        int f  = i * 256 + tid;
        int n  = f & 127;
        int k4 = (f >> 7) << 2;
        float w0 = __ldg(&W[(h * 64 + k4 + 0) * DD + n]);
        float w1 = __ldg(&W[(h * 64 + k4 + 1) * DD + n]);
        float w2 = __ldg(&W[(h * 64 + k4 + 2) * DD + n]);
        float w3 = __ldg(&W[(h * 64 + k4 + 3) * DD + n]);
        uint2 hh, ll;
        split2(w0, w1, hh.x, ll.x);
        split2(w2, w3, hh.y, ll.y);
        int off = (n * AP1 + k4) * 2;
        *(uint2*)(sm_ + oBh + off) = hh;
        *(uint2*)(sm_ + oBl + off) = ll;
    }
}

__global__ void __launch_bounds__(256, 2)
k_layer(const float* __restrict__ W1, const float* __restrict__ b1,
        const float* __restrict__ W2, const float* __restrict__ b2,
        int do_relu2) {
    extern __shared__ char sm_[];
    int tid  = threadIdx.x;
    int lane = tid & 31;
    int w    = tid >> 5;
    int wm   = w >> 2;
    int wn   = w & 3;
    int g    = lane >> 2;
    int tig  = lane & 3;
    int row0 = blockIdx.x * 128;

    float acc[4][4][4];
    #pragma unroll
    for (int i = 0; i < 4; i++)
        #pragma unroll
        for (int j = 0; j < 4; j++)
            #pragma unroll
            for (int q = 0; q < 4; q++) acc[i][j][q] = 0.0f;

    // ================= phase 1: acc = g_a @ W1 =================
    for (int h = 0; h < 2; h++) {
        // A chunk: 128 rows x 64 k from g_a (fp32 -> split bf16 hi/lo)
        #pragma unroll
        for (int i = 0; i < 8; i++) {
            int f  = i * 256 + tid;
            int m  = f >> 4;
            int k4 = (f & 15) << 2;
            float4 v = make_float4(0.f, 0.f, 0.f, 0.f);
            int gr = row0 + m;
            if (gr < NN) v = *(const float4*)&g_a[gr * DD + h * 64 + k4];
            uint2 hh, ll;
            split2(v.x, v.y, hh.x, ll.x);
            split2(v.z, v.w, hh.y, ll.y);
            int off = (m * AP1 + k4) * 2;
            *(uint2*)(sm_ + O_A1H + off) = hh;
            *(uint2*)(sm_ + O_A1L + off) = ll;
        }
        load_B_chunk(sm_, O_B1H, O_B1L, W1, h, tid);
        __syncthreads();
        #pragma unroll
        for (int ks = 0; ks < 4; ks++)
            mma_step(acc, sm_, O_A1H, O_A1L, AP1, 0, O_B1H, O_B1L, ks * 16, wm, wn, lane);
        __syncthreads();   // before T overwrites sA/sB regions
    }

    // ================= T = relu(acc + b1) -> split into T region =================
    #pragma unroll
    for (int nt = 0; nt < 4; nt++) {
        int c = wn * 32 + nt * 8 + tig * 2;
        float bb0 = __ldg(&b1[c]);
        float bb1 = __ldg(&b1[c + 1]);
        #pragma unroll
        for (int mt = 0; mt < 4; mt++) {
            float v0 = fmaxf(acc[mt][nt][0] + bb0, 0.f);
            float v1 = fmaxf(acc[mt][nt][1] + bb1, 0.f);
            float v2 = fmaxf(acc[mt][nt][2] + bb0, 0.f);
            float v3 = fmaxf(acc[mt][nt][3] + bb1, 0.f);
            uint32_t h0, l0, h1, l1;
            split2(v0, v1, h0, l0);
            split2(v2, v3, h1, l1);
            int r = wm * 64 + mt * 16 + g;
            *(uint32_t*)(sm_ + O_TH + (r * AP2 + c) * 2) = h0;
            *(uint32_t*)(sm_ + O_TL + (r * AP2 + c) * 2) = l0;
            *(uint32_t*)(sm_ + O_TH + ((r + 8) * AP2 + c) * 2) = h1;
            *(uint32_t*)(sm_ + O_TL + ((r + 8) * AP2 + c) * 2) = l1;
            acc[mt][nt][0] = 0.f; acc[mt][nt][1] = 0.f;
            acc[mt][nt][2] = 0.f; acc[mt][nt][3] = 0.f;
        }
    }

    // ================= phase 2: acc = T @ W2 =================
    for (int h = 0; h < 2; h++) {
        load_B_chunk(sm_, O_B2H, O_B2L, W2, h, tid);
        __syncthreads();   // T stores + B chunk ready
        #pragma unroll
        for (int ks = 0; ks < 4; ks++)
            mma_step(acc, sm_, O_TH, O_TL, AP2, h * 64, O_B2H, O_B2L, ks * 16, wm, wn, lane);
        __syncthreads();
    }

    // ================= epilogue: bias + act -> fp16 g_hh =================
    #pragma unroll
    for (int nt = 0; nt < 4; nt++) {
        int c = wn * 32 + nt * 8 + tig * 2;
        float bb0 = __ldg(&b2[c]);
        float bb1 = __ldg(&b2[c + 1]);
        #pragma unroll
        for (int mt = 0; mt < 4; mt++) {
            int r = row0 + wm * 64 + mt * 16 + g;
            float2 v0 = make_float2(acc[mt][nt][0] + bb0, acc[mt][nt][1] + bb1);
            float2 v1 = make_float2(acc[mt][nt][2] + bb0, acc[mt][nt][3] + bb1);
            if (do_relu2) {
                v0.x = fmaxf(v0.x, 0.f); v0.y = fmaxf(v0.y, 0.f);
                v1.x = fmaxf(v1.x, 0.f); v1.y = fmaxf(v1.y, 0.f);
            }
            if (r < NN)
                *(__half2*)&g_hh[r * DD + c] = __floats2half2_rn(v0.x, v0.y);
            if (r + 8 < NN)
                *(__half2*)&g_hh[(r + 8) * DD + c] = __floats2half2_rn(v1.x, v1.y);
        }
    }
}

// ---------------- global max pool (reads fp16 g_hh, one thread per COLUMN) ----------------
__global__ void k_initout(float* __restrict__ out) {
    int i = blockIdx.x * blockDim.x + threadIdx.x;
    if (i < NG * DD) out[i] = __int_as_float(0xFF800000);
}
__global__ void k_pool(const int* __restrict__ batch, float* __restrict__ out) {
    int t  = threadIdx.x;                 // column 0..127 (scalar fp16 loads)
    int n0 = blockIdx.x * 128;
    int cur = -1;
    float run = __int_as_float(0xFF800000);
    const __half* __restrict__ hh = g_hh;
    for (int r = 0; r < 128; r++) {
        int i = n0 + r;
        if (i >= NN) break;
        int g = batch[i];
        if (g != cur) {
            if (cur >= 0) atomicMaxF(&out[cur * DD + t], run);
            cur = g;
            run = __int_as_float(0xFF800000);
        }
        float v = __half2float(__ldg(&hh[i * DD + t]));
        run = fmaxf(run, v);
    }
    if (cur >= 0) atomicMaxF(&out[cur * DD + t], run);
}

// ---------------- launch ----------------
extern "C" void kernel_launch(void* const* d_in, const int* in_sizes, int n_in,
                              void* d_out, int out_size) {
    const float* x     = (const float*)d_in[0];
    const int*   ei    = (const int*)d_in[1];
    const int*   batch = (const int*)d_in[2];
    const float* W1    = (const float*)d_in[3];
    const float* b1    = (const float*)d_in[4];
    const float* W2    = (const float*)d_in[5];
    const float* b2    = (const float*)d_in[6];
    float* out = (float*)d_out;

    const int* src = ei;
    const int* dst = ei + NE;

    cudaFuncSetAttribute(k_layer, cudaFuncAttributeMaxDynamicSharedMemorySize, SM_LAYER);

    // independent prep
    k_x2h<<<(NN * 32 + 255) / 256, 256>>>(x);

    // CSR build (g_cnt is 0 on entry; scatter restores it to 0)
    k_hist<<<(NE + 255) / 256, 256>>>(dst);
    k_scan1<<<NSCAN, SCAN_B>>>();
    k_scan23<<<(NN + 256) / 256, 256>>>();
    k_scatter<<<(NE + 255) / 256, 256>>>(src, dst);

    // 3 GIN layers: fp16 gather + fused MLP
    int layer_blocks = (NN + 127) / 128;   // 782
    int agg_blocks   = (NN + 3) / 4;
    for (int l = 0; l < 3; l++) {
        k_agg<<<agg_blocks, 128>>>(l == 0 ? 1 : 0);
        k_layer<<<layer_blocks, 256, SM_LAYER>>>(W1 + l * DD * DD, b1 + l * DD,
                                                 W2 + l * DD * DD, b2 + l * DD,
                                                 (l < 2) ? 1 : 0);
    }

    // global max pool
    k_initout<<<(NG * DD + 255) / 256, 256>>>(out);
    k_pool<<<(NN + 127) / 128, 128>>>(batch, out);
}